// round 10
// baseline (speedup 1.0000x reference)
#include <cuda_runtime.h>
#include <cuda_bf16.h>
#include <cstdint>
#include <cstddef>

// ---------------------------------------------------------------------------
// Problem constants (fixed by the reference)
// ---------------------------------------------------------------------------
#define BB    32            // batch
#define UU    256           // U_MAX
#define TT    257           // U+1 steps
#define HH    1024          // hidden
#define GG    3072          // 3*H
#define VV    10001         // vocab
#define MM    (BB * TT)     // 8224 rows (m = b*257 + t)

#define RNN_CTAS 128

// ---------------------------------------------------------------------------
// Scratch (device globals -- no runtime allocation allowed)
// ---------------------------------------------------------------------------
__device__ __align__(16) float g_X [(size_t)MM * HH];   // gathered embeddings  [m][k]
__device__ __align__(16) float g_G0[(size_t)MM * GG];   // gi0 = X@Wih0^T + bih0 [m][3H]
__device__ __align__(16) float g_H1[(size_t)MM * HH];   // layer-1 states        [m][k]
__device__ __align__(16) float g_h0T[2][BB * HH];       // h0 transposed [k][b], double buffered
__device__ __align__(16) float g_h1T[2][BB * HH];       // h1 transposed [k][b]
__device__ unsigned          g_bar_count;
__device__ volatile unsigned g_bar_gen;

// ---------------------------------------------------------------------------
// Embedding gather: X[m][*] = embed[token(b,t)][*],  m = b*257 + t
// ---------------------------------------------------------------------------
__global__ void gather_embed(const int* __restrict__ y,
                             const float* __restrict__ embed,
                             float* __restrict__ X)
{
    int m = blockIdx.x;                 // 0..8223
    int b = m / TT, t = m % TT;
    int tok = (t == 0) ? (VV - 1) : y[b * UU + (t - 1)];
    const float4* src = (const float4*)(embed + (size_t)tok * HH);
    float4*       dst = (float4*)(X + (size_t)m * HH);
    dst[threadIdx.x] = src[threadIdx.x];        // 256 threads * float4 = 1024 floats
}

// ---------------------------------------------------------------------------
// Init transposed states from init_state (broadcast over batch)
// ---------------------------------------------------------------------------
__global__ void init_states(const float* __restrict__ init_state)
{
    int idx = blockIdx.x * blockDim.x + threadIdx.x;   // 0..32767
    int k = idx >> 5;                                  // idx = k*32 + b
    g_h0T[0][idx] = init_state[k];
    g_h1T[0][idx] = init_state[HH + k];
}

// ---------------------------------------------------------------------------
// fp32 SGEMM:  C[M][N] = A[M][K] * B[N][K]^T + bias[N]
// classic 128x128x8 blocking, 256 threads, 8x8 microtile, gmem prefetch
// ---------------------------------------------------------------------------
__global__ void __launch_bounds__(256, 2)
sgemm_bias_tn(const float* __restrict__ A,
              const float* __restrict__ B,
              const float* __restrict__ bias,
              float* __restrict__ C,
              int M, int N, int K)
{
    constexpr int BM = 128, BN = 128, BK = 8;
    __shared__ __align__(16) float As[BK][BM];
    __shared__ __align__(16) float Bs[BK][BN];

    const int tid = threadIdx.x;
    const int m0 = blockIdx.y * BM;
    const int n0 = blockIdx.x * BN;

    const int lr = tid >> 1;            // 0..127 tile row
    const int lc = (tid & 1) << 2;      // 0 or 4  (k offset)
    const int tx = (tid & 15) << 3;     // col offset of microtile
    const int ty = (tid >> 4) << 3;     // row offset of microtile

    float acc[8][8];
    #pragma unroll
    for (int i = 0; i < 8; ++i)
        #pragma unroll
        for (int jj = 0; jj < 8; ++jj) acc[i][jj] = 0.0f;

    const int  gmA = m0 + lr;
    const int  gnB = n0 + lr;
    const bool va = gmA < M;
    const bool vb = gnB < N;
    const float* Aptr = A + (size_t)gmA * K + lc;
    const float* Bptr = B + (size_t)gnB * K + lc;

    float4 pa = va ? *(const float4*)Aptr : make_float4(0.f, 0.f, 0.f, 0.f);
    float4 pb = vb ? *(const float4*)Bptr : make_float4(0.f, 0.f, 0.f, 0.f);

    const int KT = K / BK;
    for (int kt = 0; kt < KT; ++kt) {
        As[lc + 0][lr] = pa.x; As[lc + 1][lr] = pa.y; As[lc + 2][lr] = pa.z; As[lc + 3][lr] = pa.w;
        Bs[lc + 0][lr] = pb.x; Bs[lc + 1][lr] = pb.y; Bs[lc + 2][lr] = pb.z; Bs[lc + 3][lr] = pb.w;
        __syncthreads();

        if (kt + 1 < KT) {
            pa = va ? *(const float4*)(Aptr + (kt + 1) * BK) : make_float4(0.f, 0.f, 0.f, 0.f);
            pb = vb ? *(const float4*)(Bptr + (kt + 1) * BK) : make_float4(0.f, 0.f, 0.f, 0.f);
        }

        #pragma unroll
        for (int kk = 0; kk < BK; ++kk) {
            float a[8], b[8];
            *(float4*)(a)     = *(const float4*)&As[kk][ty];
            *(float4*)(a + 4) = *(const float4*)&As[kk][ty + 4];
            *(float4*)(b)     = *(const float4*)&Bs[kk][tx];
            *(float4*)(b + 4) = *(const float4*)&Bs[kk][tx + 4];
            #pragma unroll
            for (int i = 0; i < 8; ++i)
                #pragma unroll
                for (int jj = 0; jj < 8; ++jj)
                    acc[i][jj] = fmaf(a[i], b[jj], acc[i][jj]);
        }
        __syncthreads();
    }

    #pragma unroll
    for (int i = 0; i < 8; ++i) {
        int gm = m0 + ty + i;
        if (gm < M) {
            float* Crow = C + (size_t)gm * N;
            #pragma unroll
            for (int jj = 0; jj < 8; ++jj) {
                int gn = n0 + tx + jj;
                if (gn < N) Crow[gn] = acc[i][jj] + bias[gn];
            }
        }
    }
}

// ---------------------------------------------------------------------------
// Persistent recurrent kernel
// ---------------------------------------------------------------------------
__device__ __forceinline__ float sigmoidf_(float x) { return 1.0f / (1.0f + __expf(-x)); }

__device__ __forceinline__ void grid_barrier()
{
    __syncthreads();
    if (threadIdx.x == 0) {
        __threadfence();
        unsigned gen = g_bar_gen;
        if (atomicAdd(&g_bar_count, 1u) == RNN_CTAS - 1) {
            atomicExch(&g_bar_count, 0u);
            __threadfence();
            g_bar_gen = gen + 1;
        } else {
            while (g_bar_gen == gen) { __nanosleep(64); }
        }
        __threadfence();
    }
    __syncthreads();
}

// acc (4 b's) += sum over 4 k of x_k[4b] * w_k
__device__ __forceinline__ void fma16(float4& a, const float4 w,
                                      const float4& x0, const float4& x1,
                                      const float4& x2, const float4& x3)
{
    a.x = fmaf(x0.x, w.x, a.x); a.y = fmaf(x0.y, w.x, a.y); a.z = fmaf(x0.z, w.x, a.z); a.w = fmaf(x0.w, w.x, a.w);
    a.x = fmaf(x1.x, w.y, a.x); a.y = fmaf(x1.y, w.y, a.y); a.z = fmaf(x1.z, w.y, a.z); a.w = fmaf(x1.w, w.y, a.w);
    a.x = fmaf(x2.x, w.z, a.x); a.y = fmaf(x2.y, w.z, a.y); a.z = fmaf(x2.z, w.z, a.z); a.w = fmaf(x2.w, w.z, a.w);
    a.x = fmaf(x3.x, w.w, a.x); a.y = fmaf(x3.y, w.w, a.y); a.z = fmaf(x3.z, w.w, a.z); a.w = fmaf(x3.w, w.w, a.w);
}

// thread = (bq in 0..7, jl in 0..7, ks in 0..3); CTA owns j = blockIdx.x*8 + jl
// each thread accumulates a 4-batch column over a 256-wide K slice; ks-slices
// are reduced through SMEM; ks==0 threads apply gate math.
__global__ void __launch_bounds__(256, 1)
rnn_persistent(const float* __restrict__ Whh0, const float* __restrict__ bhh0,
               const float* __restrict__ Wih1, const float* __restrict__ bih1,
               const float* __restrict__ Whh1, const float* __restrict__ bhh1,
               const float* __restrict__ G0,   float* __restrict__ H1)
{
    __shared__ float red[24 * 256];

    const int tid = threadIdx.x;
    const int bq  = tid & 7;
    const int jl  = (tid >> 3) & 7;
    const int ks  = tid >> 6;
    const int j   = blockIdx.x * 8 + jl;
    const int b0  = bq << 2;
    const int kb  = ks << 8;                      // k-slice start

    const float4* w0r  = (const float4*)(Whh0 + (size_t)j * HH + kb);
    const float4* w0z  = (const float4*)(Whh0 + (size_t)(HH + j) * HH + kb);
    const float4* w0n  = (const float4*)(Whh0 + (size_t)(2 * HH + j) * HH + kb);
    const float4* w1ir = (const float4*)(Wih1 + (size_t)j * HH + kb);
    const float4* w1iz = (const float4*)(Wih1 + (size_t)(HH + j) * HH + kb);
    const float4* w1in = (const float4*)(Wih1 + (size_t)(2 * HH + j) * HH + kb);
    const float4* w1hr = (const float4*)(Whh1 + (size_t)j * HH + kb);
    const float4* w1hz = (const float4*)(Whh1 + (size_t)(HH + j) * HH + kb);
    const float4* w1hn = (const float4*)(Whh1 + (size_t)(2 * HH + j) * HH + kb);

    for (int t = 0; t < TT; ++t) {
        const int cur = t & 1, nxt = cur ^ 1;
        const float* h0c = g_h0T[cur];
        float*       h0n = g_h0T[nxt];
        const float* h1c = g_h1T[cur];
        float*       h1n = g_h1T[nxt];

        // ------------------------- layer 0: gh = h0 @ Whh0^T -------------------------
        {
            float4 ar = {0,0,0,0}, az = {0,0,0,0}, an = {0,0,0,0};
            const float4* xp = (const float4*)(h0c + kb * BB) + bq;    // [k][b0..b0+3]
            #pragma unroll 4
            for (int kk = 0; kk < 64; ++kk) {
                float4 wr = w0r[kk], wz = w0z[kk], wn = w0n[kk];
                float4 x0 = xp[(kk * 4 + 0) * 8];
                float4 x1 = xp[(kk * 4 + 1) * 8];
                float4 x2 = xp[(kk * 4 + 2) * 8];
                float4 x3 = xp[(kk * 4 + 3) * 8];
                fma16(ar, wr, x0, x1, x2, x3);
                fma16(az, wz, x0, x1, x2, x3);
                fma16(an, wn, x0, x1, x2, x3);
            }
            float vals[12] = {ar.x, ar.y, ar.z, ar.w,
                              az.x, az.y, az.z, az.w,
                              an.x, an.y, an.z, an.w};
            #pragma unroll
            for (int c = 0; c < 12; ++c) red[c * 256 + tid] = vals[c];
            __syncthreads();

            if (tid < 64) {
                float s[12];
                #pragma unroll
                for (int c = 0; c < 12; ++c)
                    s[c] = red[c * 256 + tid]       + red[c * 256 + tid + 64]
                         + red[c * 256 + tid + 128] + red[c * 256 + tid + 192];
                const float bhr = bhh0[j], bhz = bhh0[HH + j], bhn = bhh0[2 * HH + j];
                float hold[4];
                *(float4*)hold = *(const float4*)(h0c + j * BB + b0);
                float hnew[4];
                #pragma unroll
                for (int i = 0; i < 4; ++i) {
                    const int b = b0 + i;
                    const float* gi = G0 + ((size_t)b * TT + t) * GG;
                    float r = sigmoidf_(gi[j]          + s[i]     + bhr);
                    float z = sigmoidf_(gi[HH + j]     + s[4 + i] + bhz);
                    float n = tanhf    (gi[2 * HH + j] + r * (s[8 + i] + bhn));
                    hnew[i] = n + z * (hold[i] - n);
                }
                *(float4*)(h0n + j * BB + b0) = *(float4*)hnew;
            }
        }
        grid_barrier();

        // ------------ layer 1: gi = h0new @ Wih1^T ; gh = h1 @ Whh1^T ---------------
        {
            float4 air = {0,0,0,0}, aiz = {0,0,0,0}, ain = {0,0,0,0};
            float4 ahr = {0,0,0,0}, ahz = {0,0,0,0}, ahn = {0,0,0,0};
            const float4* xp = (const float4*)(h0n + kb * BB) + bq;
            const float4* hp = (const float4*)(h1c + kb * BB) + bq;
            #pragma unroll 2
            for (int kk = 0; kk < 64; ++kk) {
                float4 wir = w1ir[kk], wiz = w1iz[kk], win = w1in[kk];
                float4 whr = w1hr[kk], whz = w1hz[kk], whn = w1hn[kk];
                float4 x0 = xp[(kk * 4 + 0) * 8];
                float4 x1 = xp[(kk * 4 + 1) * 8];
                float4 x2 = xp[(kk * 4 + 2) * 8];
                float4 x3 = xp[(kk * 4 + 3) * 8];
                fma16(air, wir, x0, x1, x2, x3);
                fma16(aiz, wiz, x0, x1, x2, x3);
                fma16(ain, win, x0, x1, x2, x3);
                float4 h0_ = hp[(kk * 4 + 0) * 8];
                float4 h1_ = hp[(kk * 4 + 1) * 8];
                float4 h2_ = hp[(kk * 4 + 2) * 8];
                float4 h3_ = hp[(kk * 4 + 3) * 8];
                fma16(ahr, whr, h0_, h1_, h2_, h3_);
                fma16(ahz, whz, h0_, h1_, h2_, h3_);
                fma16(ahn, whn, h0_, h1_, h2_, h3_);
            }
            float vals[24] = {air.x, air.y, air.z, air.w,  aiz.x, aiz.y, aiz.z, aiz.w,
                              ain.x, ain.y, ain.z, ain.w,  ahr.x, ahr.y, ahr.z, ahr.w,
                              ahz.x, ahz.y, ahz.z, ahz.w,  ahn.x, ahn.y, ahn.z, ahn.w};
            #pragma unroll
            for (int c = 0; c < 24; ++c) red[c * 256 + tid] = vals[c];
            __syncthreads();

            if (tid < 64) {
                float s[24];
                #pragma unroll
                for (int c = 0; c < 24; ++c)
                    s[c] = red[c * 256 + tid]       + red[c * 256 + tid + 64]
                         + red[c * 256 + tid + 128] + red[c * 256 + tid + 192];
                const float bir = bih1[j], biz = bih1[HH + j], bin_ = bih1[2 * HH + j];
                const float bhr = bhh1[j], bhz = bhh1[HH + j], bhn  = bhh1[2 * HH + j];
                float hold[4];
                *(float4*)hold = *(const float4*)(h1c + j * BB + b0);
                float hnew[4];
                #pragma unroll
                for (int i = 0; i < 4; ++i) {
                    const int b = b0 + i;
                    float r = sigmoidf_((s[i]      + bir) + (s[12 + i] + bhr));
                    float z = sigmoidf_((s[4 + i]  + biz) + (s[16 + i] + bhz));
                    float n = tanhf    ((s[8 + i]  + bin_) + r * (s[20 + i] + bhn));
                    hnew[i] = n + z * (hold[i] - n);
                    H1[((size_t)b * TT + t) * HH + j] = hnew[i];
                }
                *(float4*)(h1n + j * BB + b0) = *(float4*)hnew;
            }
        }
        grid_barrier();
    }
}

// ---------------------------------------------------------------------------
// Launch
// ---------------------------------------------------------------------------
extern "C" void kernel_launch(void* const* d_in, const int* in_sizes, int n_in,
                              void* d_out, int out_size)
{
    // Identify inputs by element counts (robust to the scalar "U" being present
    // or absent). Duplicate sizes are resolved by dict order: embed before Wout,
    // Wih before Whh, bih before bhh.
    const int*   y     = nullptr;
    const float* embed = nullptr;
    const float* initS = nullptr;
    const float* Wih   = nullptr;
    const float* Whh   = nullptr;
    const float* bih   = nullptr;
    const float* bhh   = nullptr;
    const float* Wout  = nullptr;
    const float* bout  = nullptr;

    for (int i = 0; i < n_in; ++i) {
        long long s = in_sizes[i];
        if (s == (long long)BB * UU && !y)               y     = (const int*)d_in[i];
        else if (s == (long long)VV * HH) {
            if (!embed)                                  embed = (const float*)d_in[i];
            else if (!Wout)                              Wout  = (const float*)d_in[i];
        }
        else if (s == 2LL * HH && !initS)                initS = (const float*)d_in[i];
        else if (s == 2LL * GG * HH) {
            if (!Wih)                                    Wih   = (const float*)d_in[i];
            else if (!Whh)                               Whh   = (const float*)d_in[i];
        }
        else if (s == 2LL * GG) {
            if (!bih)                                    bih   = (const float*)d_in[i];
            else if (!bhh)                               bhh   = (const float*)d_in[i];
        }
        else if (s == (long long)VV && !bout)            bout  = (const float*)d_in[i];
    }

    float *pX = nullptr, *pG0 = nullptr, *pH1 = nullptr;
    cudaGetSymbolAddress((void**)&pX,  g_X);
    cudaGetSymbolAddress((void**)&pG0, g_G0);
    cudaGetSymbolAddress((void**)&pH1, g_H1);

    // 1) gather embeddings into X[m][k], m = b*257 + t
    gather_embed<<<MM, 256>>>(y, embed, pX);

    // 2) init transposed recurrent state buffers
    init_states<<<128, 256>>>(initS);

    // 3) gi0 = X @ Wih0^T + bih0   (8224 x 3072 x 1024)
    sgemm_bias_tn<<<dim3(GG / 128, (MM + 127) / 128), 256>>>(
        pX, Wih, bih, pG0, MM, GG, HH);

    // 4) persistent 257-step recurrence -> H1[m][k]
    rnn_persistent<<<RNN_CTAS, 256>>>(
        Whh, bhh,
        Wih + (size_t)GG * HH, bih + GG,
        Whh + (size_t)GG * HH, bhh + GG,
        pG0, pH1);

    // 5) OUT = H1 @ Wout^T + bout  (8224 x 10001 x 1024) -> d_out (B, U+1, V)
    sgemm_bias_tn<<<dim3((VV + 127) / 128, (MM + 127) / 128), 256>>>(
        pH1, Wout, bout, (float*)d_out, MM, VV, HH);

    (void)n_in; (void)out_size;
}

// round 11
// speedup vs baseline: 1.0029x; 1.0029x over previous
#include <cuda_runtime.h>
#include <cuda_bf16.h>
#include <cstdint>
#include <cstddef>

// ---------------------------------------------------------------------------
// Problem constants (fixed by the reference)
// ---------------------------------------------------------------------------
#define BB    32            // batch
#define UU    256           // U_MAX
#define TT    257           // U+1 steps
#define HH    1024          // hidden
#define GG    3072          // 3*H
#define VV    10001         // vocab
#define MM    (BB * TT)     // 8224 rows (m = b*257 + t)

#define RNN_CTAS 128

// ---------------------------------------------------------------------------
// Scratch (device globals -- no runtime allocation allowed)
// ---------------------------------------------------------------------------
__device__ __align__(16) float g_X [(size_t)MM * HH];   // gathered embeddings  [m][k]
__device__ __align__(16) float g_G0[(size_t)MM * GG];   // gi0 = X@Wih0^T + bih0 [m][3H]
__device__ __align__(16) float g_H1[(size_t)MM * HH];   // layer-1 states        [m][k]
__device__ __align__(16) float g_h0T[2][BB * HH];       // h0 transposed [k][b], double buffered
__device__ __align__(16) float g_h1T[2][BB * HH];       // h1 transposed [k][b]
__device__ unsigned          g_bar_count;
__device__ volatile unsigned g_bar_gen;

// ---------------------------------------------------------------------------
// Embedding gather: X[m][*] = embed[token(b,t)][*],  m = b*257 + t
// ---------------------------------------------------------------------------
__global__ void gather_embed(const int* __restrict__ y,
                             const float* __restrict__ embed,
                             float* __restrict__ X)
{
    int m = blockIdx.x;                 // 0..8223
    int b = m / TT, t = m % TT;
    int tok = (t == 0) ? (VV - 1) : y[b * UU + (t - 1)];
    const float4* src = (const float4*)(embed + (size_t)tok * HH);
    float4*       dst = (float4*)(X + (size_t)m * HH);
    dst[threadIdx.x] = src[threadIdx.x];        // 256 threads * float4 = 1024 floats
}

// ---------------------------------------------------------------------------
// Init transposed states from init_state (broadcast over batch)
// ---------------------------------------------------------------------------
__global__ void init_states(const float* __restrict__ init_state)
{
    int idx = blockIdx.x * blockDim.x + threadIdx.x;   // 0..32767
    int k = idx >> 5;                                  // idx = k*32 + b
    g_h0T[0][idx] = init_state[k];
    g_h1T[0][idx] = init_state[HH + k];
}

// ---------------------------------------------------------------------------
// fp32 SGEMM:  C[M][N] = A[M][K] * B[N][K]^T + bias[N]
// classic 128x128x8 blocking, 256 threads, 8x8 microtile, gmem prefetch
// ---------------------------------------------------------------------------
__global__ void __launch_bounds__(256, 2)
sgemm_bias_tn(const float* __restrict__ A,
              const float* __restrict__ B,
              const float* __restrict__ bias,
              float* __restrict__ C,
              int M, int N, int K)
{
    constexpr int BM = 128, BN = 128, BK = 8;
    __shared__ __align__(16) float As[BK][BM];
    __shared__ __align__(16) float Bs[BK][BN];

    const int tid = threadIdx.x;
    const int m0 = blockIdx.y * BM;
    const int n0 = blockIdx.x * BN;

    const int lr = tid >> 1;            // 0..127 tile row
    const int lc = (tid & 1) << 2;      // 0 or 4  (k offset)
    const int tx = (tid & 15) << 3;     // col offset of microtile
    const int ty = (tid >> 4) << 3;     // row offset of microtile

    float acc[8][8];
    #pragma unroll
    for (int i = 0; i < 8; ++i)
        #pragma unroll
        for (int jj = 0; jj < 8; ++jj) acc[i][jj] = 0.0f;

    const int  gmA = m0 + lr;
    const int  gnB = n0 + lr;
    const bool va = gmA < M;
    const bool vb = gnB < N;
    const float* Aptr = A + (size_t)gmA * K + lc;
    const float* Bptr = B + (size_t)gnB * K + lc;

    float4 pa = va ? *(const float4*)Aptr : make_float4(0.f, 0.f, 0.f, 0.f);
    float4 pb = vb ? *(const float4*)Bptr : make_float4(0.f, 0.f, 0.f, 0.f);

    const int KT = K / BK;
    for (int kt = 0; kt < KT; ++kt) {
        As[lc + 0][lr] = pa.x; As[lc + 1][lr] = pa.y; As[lc + 2][lr] = pa.z; As[lc + 3][lr] = pa.w;
        Bs[lc + 0][lr] = pb.x; Bs[lc + 1][lr] = pb.y; Bs[lc + 2][lr] = pb.z; Bs[lc + 3][lr] = pb.w;
        __syncthreads();

        if (kt + 1 < KT) {
            pa = va ? *(const float4*)(Aptr + (kt + 1) * BK) : make_float4(0.f, 0.f, 0.f, 0.f);
            pb = vb ? *(const float4*)(Bptr + (kt + 1) * BK) : make_float4(0.f, 0.f, 0.f, 0.f);
        }

        #pragma unroll
        for (int kk = 0; kk < BK; ++kk) {
            float a[8], b[8];
            *(float4*)(a)     = *(const float4*)&As[kk][ty];
            *(float4*)(a + 4) = *(const float4*)&As[kk][ty + 4];
            *(float4*)(b)     = *(const float4*)&Bs[kk][tx];
            *(float4*)(b + 4) = *(const float4*)&Bs[kk][tx + 4];
            #pragma unroll
            for (int i = 0; i < 8; ++i)
                #pragma unroll
                for (int jj = 0; jj < 8; ++jj)
                    acc[i][jj] = fmaf(a[i], b[jj], acc[i][jj]);
        }
        __syncthreads();
    }

    #pragma unroll
    for (int i = 0; i < 8; ++i) {
        int gm = m0 + ty + i;
        if (gm < M) {
            float* Crow = C + (size_t)gm * N;
            #pragma unroll
            for (int jj = 0; jj < 8; ++jj) {
                int gn = n0 + tx + jj;
                if (gn < N) Crow[gn] = acc[i][jj] + bias[gn];
            }
        }
    }
}

// ---------------------------------------------------------------------------
// Persistent recurrent kernel
// ---------------------------------------------------------------------------
__device__ __forceinline__ float sigmoidf_(float x) { return 1.0f / (1.0f + __expf(-x)); }

__device__ __forceinline__ void grid_barrier()
{
    __syncthreads();
    if (threadIdx.x == 0) {
        __threadfence();
        unsigned gen = g_bar_gen;
        if (atomicAdd(&g_bar_count, 1u) == RNN_CTAS - 1) {
            atomicExch(&g_bar_count, 0u);
            __threadfence();
            g_bar_gen = gen + 1;
        } else {
            while (g_bar_gen == gen) { __nanosleep(64); }
        }
        __threadfence();
    }
    __syncthreads();
}

// acc (4 b's) += sum over 4 k of x_k[4b] * w_k
__device__ __forceinline__ void fma16(float4& a, const float4 w,
                                      const float4& x0, const float4& x1,
                                      const float4& x2, const float4& x3)
{
    a.x = fmaf(x0.x, w.x, a.x); a.y = fmaf(x0.y, w.x, a.y); a.z = fmaf(x0.z, w.x, a.z); a.w = fmaf(x0.w, w.x, a.w);
    a.x = fmaf(x1.x, w.y, a.x); a.y = fmaf(x1.y, w.y, a.y); a.z = fmaf(x1.z, w.y, a.z); a.w = fmaf(x1.w, w.y, a.w);
    a.x = fmaf(x2.x, w.z, a.x); a.y = fmaf(x2.y, w.z, a.y); a.z = fmaf(x2.z, w.z, a.z); a.w = fmaf(x2.w, w.z, a.w);
    a.x = fmaf(x3.x, w.w, a.x); a.y = fmaf(x3.y, w.w, a.y); a.z = fmaf(x3.z, w.w, a.z); a.w = fmaf(x3.w, w.w, a.w);
}

// thread = (bq in 0..7, jl in 0..7, ks in 0..3); CTA owns j = blockIdx.x*8 + jl
// each thread accumulates a 4-batch column over a 256-wide K slice; ks-slices
// are reduced through SMEM; ks==0 threads apply gate math.
__global__ void __launch_bounds__(256, 1)
rnn_persistent(const float* __restrict__ Whh0, const float* __restrict__ bhh0,
               const float* __restrict__ Wih1, const float* __restrict__ bih1,
               const float* __restrict__ Whh1, const float* __restrict__ bhh1,
               const float* __restrict__ G0,   float* __restrict__ H1)
{
    __shared__ float red[24 * 256];

    const int tid = threadIdx.x;
    const int bq  = tid & 7;
    const int jl  = (tid >> 3) & 7;
    const int ks  = tid >> 6;
    const int j   = blockIdx.x * 8 + jl;
    const int b0  = bq << 2;
    const int kb  = ks << 8;                      // k-slice start

    const float4* w0r  = (const float4*)(Whh0 + (size_t)j * HH + kb);
    const float4* w0z  = (const float4*)(Whh0 + (size_t)(HH + j) * HH + kb);
    const float4* w0n  = (const float4*)(Whh0 + (size_t)(2 * HH + j) * HH + kb);
    const float4* w1ir = (const float4*)(Wih1 + (size_t)j * HH + kb);
    const float4* w1iz = (const float4*)(Wih1 + (size_t)(HH + j) * HH + kb);
    const float4* w1in = (const float4*)(Wih1 + (size_t)(2 * HH + j) * HH + kb);
    const float4* w1hr = (const float4*)(Whh1 + (size_t)j * HH + kb);
    const float4* w1hz = (const float4*)(Whh1 + (size_t)(HH + j) * HH + kb);
    const float4* w1hn = (const float4*)(Whh1 + (size_t)(2 * HH + j) * HH + kb);

    for (int t = 0; t < TT; ++t) {
        const int cur = t & 1, nxt = cur ^ 1;
        const float* h0c = g_h0T[cur];
        float*       h0n = g_h0T[nxt];
        const float* h1c = g_h1T[cur];
        float*       h1n = g_h1T[nxt];

        // ------------------------- layer 0: gh = h0 @ Whh0^T -------------------------
        {
            float4 ar = {0,0,0,0}, az = {0,0,0,0}, an = {0,0,0,0};
            const float4* xp = (const float4*)(h0c + kb * BB) + bq;    // [k][b0..b0+3]
            #pragma unroll 4
            for (int kk = 0; kk < 64; ++kk) {
                float4 wr = w0r[kk], wz = w0z[kk], wn = w0n[kk];
                float4 x0 = xp[(kk * 4 + 0) * 8];
                float4 x1 = xp[(kk * 4 + 1) * 8];
                float4 x2 = xp[(kk * 4 + 2) * 8];
                float4 x3 = xp[(kk * 4 + 3) * 8];
                fma16(ar, wr, x0, x1, x2, x3);
                fma16(az, wz, x0, x1, x2, x3);
                fma16(an, wn, x0, x1, x2, x3);
            }
            float vals[12] = {ar.x, ar.y, ar.z, ar.w,
                              az.x, az.y, az.z, az.w,
                              an.x, an.y, an.z, an.w};
            #pragma unroll
            for (int c = 0; c < 12; ++c) red[c * 256 + tid] = vals[c];
            __syncthreads();

            if (tid < 64) {
                float s[12];
                #pragma unroll
                for (int c = 0; c < 12; ++c)
                    s[c] = red[c * 256 + tid]       + red[c * 256 + tid + 64]
                         + red[c * 256 + tid + 128] + red[c * 256 + tid + 192];
                const float bhr = bhh0[j], bhz = bhh0[HH + j], bhn = bhh0[2 * HH + j];
                float hold[4];
                *(float4*)hold = *(const float4*)(h0c + j * BB + b0);
                float hnew[4];
                #pragma unroll
                for (int i = 0; i < 4; ++i) {
                    const int b = b0 + i;
                    const float* gi = G0 + ((size_t)b * TT + t) * GG;
                    float r = sigmoidf_(gi[j]          + s[i]     + bhr);
                    float z = sigmoidf_(gi[HH + j]     + s[4 + i] + bhz);
                    float n = tanhf    (gi[2 * HH + j] + r * (s[8 + i] + bhn));
                    hnew[i] = n + z * (hold[i] - n);
                }
                *(float4*)(h0n + j * BB + b0) = *(float4*)hnew;
            }
        }
        grid_barrier();

        // ------------ layer 1: gi = h0new @ Wih1^T ; gh = h1 @ Whh1^T ---------------
        {
            float4 air = {0,0,0,0}, aiz = {0,0,0,0}, ain = {0,0,0,0};
            float4 ahr = {0,0,0,0}, ahz = {0,0,0,0}, ahn = {0,0,0,0};
            const float4* xp = (const float4*)(h0n + kb * BB) + bq;
            const float4* hp = (const float4*)(h1c + kb * BB) + bq;
            #pragma unroll 2
            for (int kk = 0; kk < 64; ++kk) {
                float4 wir = w1ir[kk], wiz = w1iz[kk], win = w1in[kk];
                float4 whr = w1hr[kk], whz = w1hz[kk], whn = w1hn[kk];
                float4 x0 = xp[(kk * 4 + 0) * 8];
                float4 x1 = xp[(kk * 4 + 1) * 8];
                float4 x2 = xp[(kk * 4 + 2) * 8];
                float4 x3 = xp[(kk * 4 + 3) * 8];
                fma16(air, wir, x0, x1, x2, x3);
                fma16(aiz, wiz, x0, x1, x2, x3);
                fma16(ain, win, x0, x1, x2, x3);
                float4 h0_ = hp[(kk * 4 + 0) * 8];
                float4 h1_ = hp[(kk * 4 + 1) * 8];
                float4 h2_ = hp[(kk * 4 + 2) * 8];
                float4 h3_ = hp[(kk * 4 + 3) * 8];
                fma16(ahr, whr, h0_, h1_, h2_, h3_);
                fma16(ahz, whz, h0_, h1_, h2_, h3_);
                fma16(ahn, whn, h0_, h1_, h2_, h3_);
            }
            float vals[24] = {air.x, air.y, air.z, air.w,  aiz.x, aiz.y, aiz.z, aiz.w,
                              ain.x, ain.y, ain.z, ain.w,  ahr.x, ahr.y, ahr.z, ahr.w,
                              ahz.x, ahz.y, ahz.z, ahz.w,  ahn.x, ahn.y, ahn.z, ahn.w};
            #pragma unroll
            for (int c = 0; c < 24; ++c) red[c * 256 + tid] = vals[c];
            __syncthreads();

            if (tid < 64) {
                float s[24];
                #pragma unroll
                for (int c = 0; c < 24; ++c)
                    s[c] = red[c * 256 + tid]       + red[c * 256 + tid + 64]
                         + red[c * 256 + tid + 128] + red[c * 256 + tid + 192];
                const float bir = bih1[j], biz = bih1[HH + j], bin_ = bih1[2 * HH + j];
                const float bhr = bhh1[j], bhz = bhh1[HH + j], bhn  = bhh1[2 * HH + j];
                float hold[4];
                *(float4*)hold = *(const float4*)(h1c + j * BB + b0);
                float hnew[4];
                #pragma unroll
                for (int i = 0; i < 4; ++i) {
                    const int b = b0 + i;
                    float r = sigmoidf_((s[i]      + bir) + (s[12 + i] + bhr));
                    float z = sigmoidf_((s[4 + i]  + biz) + (s[16 + i] + bhz));
                    float n = tanhf    ((s[8 + i]  + bin_) + r * (s[20 + i] + bhn));
                    hnew[i] = n + z * (hold[i] - n);
                    H1[((size_t)b * TT + t) * HH + j] = hnew[i];
                }
                *(float4*)(h1n + j * BB + b0) = *(float4*)hnew;
            }
        }
        grid_barrier();
    }
}

// ---------------------------------------------------------------------------
// Launch
// ---------------------------------------------------------------------------
extern "C" void kernel_launch(void* const* d_in, const int* in_sizes, int n_in,
                              void* d_out, int out_size)
{
    // Identify inputs by element counts (robust to the scalar "U" being present
    // or absent). Duplicate sizes are resolved by dict order: embed before Wout,
    // Wih before Whh, bih before bhh.
    const int*   y     = nullptr;
    const float* embed = nullptr;
    const float* initS = nullptr;
    const float* Wih   = nullptr;
    const float* Whh   = nullptr;
    const float* bih   = nullptr;
    const float* bhh   = nullptr;
    const float* Wout  = nullptr;
    const float* bout  = nullptr;

    for (int i = 0; i < n_in; ++i) {
        long long s = in_sizes[i];
        if (s == (long long)BB * UU && !y)               y     = (const int*)d_in[i];
        else if (s == (long long)VV * HH) {
            if (!embed)                                  embed = (const float*)d_in[i];
            else if (!Wout)                              Wout  = (const float*)d_in[i];
        }
        else if (s == 2LL * HH && !initS)                initS = (const float*)d_in[i];
        else if (s == 2LL * GG * HH) {
            if (!Wih)                                    Wih   = (const float*)d_in[i];
            else if (!Whh)                               Whh   = (const float*)d_in[i];
        }
        else if (s == 2LL * GG) {
            if (!bih)                                    bih   = (const float*)d_in[i];
            else if (!bhh)                               bhh   = (const float*)d_in[i];
        }
        else if (s == (long long)VV && !bout)            bout  = (const float*)d_in[i];
    }

    float *pX = nullptr, *pG0 = nullptr, *pH1 = nullptr;
    cudaGetSymbolAddress((void**)&pX,  g_X);
    cudaGetSymbolAddress((void**)&pG0, g_G0);
    cudaGetSymbolAddress((void**)&pH1, g_H1);

    // 1) gather embeddings into X[m][k], m = b*257 + t
    gather_embed<<<MM, 256>>>(y, embed, pX);

    // 2) init transposed recurrent state buffers
    init_states<<<128, 256>>>(initS);

    // 3) gi0 = X @ Wih0^T + bih0   (8224 x 3072 x 1024)
    sgemm_bias_tn<<<dim3(GG / 128, (MM + 127) / 128), 256>>>(
        pX, Wih, bih, pG0, MM, GG, HH);

    // 4) persistent 257-step recurrence -> H1[m][k]
    rnn_persistent<<<RNN_CTAS, 256>>>(
        Whh, bhh,
        Wih + (size_t)GG * HH, bih + GG,
        Whh + (size_t)GG * HH, bhh + GG,
        pG0, pH1);

    // 5) OUT = H1 @ Wout^T + bout  (8224 x 10001 x 1024) -> d_out (B, U+1, V)
    sgemm_bias_tn<<<dim3((VV + 127) / 128, (MM + 127) / 128), 256>>>(
        pH1, Wout, bout, (float*)d_out, MM, VV, HH);

    (void)n_in; (void)out_size;
}

// round 16
// speedup vs baseline: 1.2198x; 1.2163x over previous
#include <cuda_runtime.h>
#include <cuda_bf16.h>
#include <cstdint>
#include <cstddef>

// ---------------------------------------------------------------------------
// Problem constants
// ---------------------------------------------------------------------------
#define BB    32
#define UU    256
#define TT    257
#define HH    1024
#define GG    3072
#define VV    10001
#define MM    (BB * TT)       // 8224
#define KSPL  3072            // split K (3 x 1024)

#define RNN_CTAS 128

// ---------------------------------------------------------------------------
// Scratch (device globals -- no runtime allocation allowed)
// ---------------------------------------------------------------------------
__device__ __align__(16) __nv_bfloat16 g_Asplit[(size_t)MM * KSPL];   // 50.5 MB
__device__ __align__(16) __nv_bfloat16 g_Bsplit[(size_t)VV * KSPL];   // 61.4 MB
__device__ __align__(16) float g_G0[(size_t)MM * GG];                 // gi0
__device__ __align__(16) float g_H1[(size_t)MM * HH];                 // layer-1 states
__device__ __align__(16) float g_h0T[2][BB * HH];
__device__ __align__(16) float g_h1T[2][BB * HH];
__device__ unsigned          g_bar_count;
__device__ volatile unsigned g_bar_gen;

// ---------------------------------------------------------------------------
// Base-ISA helpers (no 'a'-suffix features: mma.sync / ldmatrix / cp.async)
// ---------------------------------------------------------------------------
__device__ __forceinline__ uint32_t smem_u32(const void* p) {
    uint32_t a;
    asm("{ .reg .u64 t; cvta.to.shared.u64 t, %1; cvt.u32.u64 %0, t; }" : "=r"(a) : "l"(p));
    return a;
}
__device__ __forceinline__ uint32_t sw128(uint32_t x) { return x ^ ((x >> 3) & 0x70); }

__device__ __forceinline__ void cp_async16(uint32_t saddr, const void* gaddr, uint32_t src_bytes) {
    asm volatile("cp.async.cg.shared.global [%0], [%1], 16, %2;"
                 :: "r"(saddr), "l"(gaddr), "r"(src_bytes) : "memory");
}
#define CP_COMMIT()   asm volatile("cp.async.commit_group;" ::: "memory")
#define CP_WAIT(n)    asm volatile("cp.async.wait_group %0;" :: "n"(n) : "memory")

__device__ __forceinline__ void ldmx4(uint32_t* r, uint32_t addr) {
    asm volatile("ldmatrix.sync.aligned.m8n8.x4.shared.b16 {%0,%1,%2,%3}, [%4];"
                 : "=r"(r[0]), "=r"(r[1]), "=r"(r[2]), "=r"(r[3]) : "r"(addr));
}
__device__ __forceinline__ void mma16816(float* c, const uint32_t* a,
                                         uint32_t b0, uint32_t b1) {
    asm volatile("mma.sync.aligned.m16n8k16.row.col.f32.bf16.bf16.f32 "
                 "{%0,%1,%2,%3}, {%4,%5,%6,%7}, {%8,%9}, {%0,%1,%2,%3};"
                 : "+f"(c[0]), "+f"(c[1]), "+f"(c[2]), "+f"(c[3])
                 : "r"(a[0]), "r"(a[1]), "r"(a[2]), "r"(a[3]), "r"(b0), "r"(b1));
}

// ---------------------------------------------------------------------------
// Split helpers: x -> (hi, lo) bf16, K-concatenated layout
// A-style row: [hi | lo | hi]   (lo_slot = 1)
// B-style row: [hi | hi | lo]   (lo_slot = 2)
// ---------------------------------------------------------------------------
__global__ void split_mat(const float* __restrict__ src, __nv_bfloat16* __restrict__ dst,
                          int R, int lo_slot)
{
    int idx = blockIdx.x * 256 + threadIdx.x;
    if (idx >= R * HH) return;
    int r = idx >> 10, k = idx & 1023;
    float x = src[idx];
    __nv_bfloat16 hi = __float2bfloat16(x);
    __nv_bfloat16 lo = __float2bfloat16(x - __bfloat162float(hi));
    __nv_bfloat16* row = dst + (size_t)r * KSPL;
    row[k]          = (lo_slot == 0) ? lo : hi;
    row[HH + k]     = (lo_slot == 1) ? lo : hi;
    row[2 * HH + k] = (lo_slot == 2) ? lo : hi;
}

__global__ void gather_split(const int* __restrict__ y,
                             const float* __restrict__ embed,
                             __nv_bfloat16* __restrict__ dst)
{
    int m = blockIdx.x;                       // m = b*257 + t
    int b = m / TT, t = m % TT;
    int tok = (t == 0) ? (VV - 1) : y[b * UU + (t - 1)];
    const float* src = embed + (size_t)tok * HH;
    __nv_bfloat16* row = dst + (size_t)m * KSPL;
    for (int k = threadIdx.x; k < HH; k += 256) {
        float x = src[k];
        __nv_bfloat16 hi = __float2bfloat16(x);
        __nv_bfloat16 lo = __float2bfloat16(x - __bfloat162float(hi));
        row[k] = hi; row[HH + k] = lo; row[2 * HH + k] = hi;
    }
}

__global__ void init_states(const float* __restrict__ init_state)
{
    int idx = blockIdx.x * blockDim.x + threadIdx.x;
    int k = idx >> 5;
    g_h0T[0][idx] = init_state[k];
    g_h1T[0][idx] = init_state[HH + k];
}

// ---------------------------------------------------------------------------
// bf16 HMMA GEMM:  C[M][N] = A'[M][3072] * B'[N][3072]^T + bias[N] (fp32 acc)
// 128x128x64 CTA tile, 8 warps (4x2), mma.sync.m16n8k16, cp.async double buffer
// SMEM: A/B tiles 128 rows x 128B (SW128 swizzle), 2 buffers = 64 KB
// ---------------------------------------------------------------------------
#define GEMM_DYN_SMEM 65536

__global__ void __launch_bounds__(256, 1)
mma_gemm_bf16(const __nv_bfloat16* __restrict__ A,
              const __nv_bfloat16* __restrict__ Bm,
              const float* __restrict__ bias,
              float* __restrict__ C,
              int M, int N, int ldc)
{
    constexpr int KCH = KSPL / 64;            // 48 stages
    extern __shared__ __align__(16) char dyn[];

    const int tid  = threadIdx.x;
    const int wid  = tid >> 5;
    const int lane = tid & 31;
    const int wm   = wid & 3;                 // warp row   (M): 4
    const int wn   = wid >> 2;                // warp col   (N): 2
    const int m0 = blockIdx.y * 128;
    const int n0 = blockIdx.x * 128;

    const uint32_t sbase = smem_u32(dyn);
    const uint32_t offA[2] = { 0u, 16384u };
    const uint32_t offB[2] = { 32768u, 49152u };

    float acc[2][8][4];
    #pragma unroll
    for (int mi = 0; mi < 2; ++mi)
        #pragma unroll
        for (int nj = 0; nj < 8; ++nj)
            #pragma unroll
            for (int q = 0; q < 4; ++q) acc[mi][nj][q] = 0.0f;

    // --- stage loader: 128x64 bf16 A and B tiles via cp.async (16B each) ---
    auto issue_stage = [&](int ch) {
        const int buf = ch & 1;
        #pragma unroll
        for (int i = 0; i < 4; ++i) {
            int idx = tid + i * 256;
            int r = idx >> 3, u = idx & 7;
            uint32_t so = sw128((uint32_t)(r * 128 + u * 16));
            int ra = (m0 + r < M) ? (m0 + r) : 0;
            uint32_t sza = (m0 + r < M) ? 16u : 0u;
            cp_async16(sbase + offA[buf] + so,
                       A + (size_t)ra * KSPL + ch * 64 + u * 8, sza);
            int rb = (n0 + r < N) ? (n0 + r) : 0;
            uint32_t szb = (n0 + r < N) ? 16u : 0u;
            cp_async16(sbase + offB[buf] + so,
                       Bm + (size_t)rb * KSPL + ch * 64 + u * 8, szb);
        }
        CP_COMMIT();
    };

    issue_stage(0);

    for (int ch = 0; ch < KCH; ++ch) {
        const int buf = ch & 1;
        if (ch + 1 < KCH) { issue_stage(ch + 1); CP_WAIT(1); }
        else              { CP_WAIT(0); }
        __syncthreads();

        const uint32_t abase = sbase + offA[buf];
        const uint32_t bbase = sbase + offB[buf];
        const int lrow = lane & 15;
        const int lch  = lane >> 4;

        #pragma unroll
        for (int kk = 0; kk < 4; ++kk) {
            const int ch16 = kk * 2 + lch;
            uint32_t afr[2][4];
            #pragma unroll
            for (int mi = 0; mi < 2; ++mi) {
                int row = wm * 32 + mi * 16 + lrow;
                ldmx4(afr[mi], abase + sw128((uint32_t)(row * 128 + ch16 * 16)));
            }
            uint32_t bfr[4][4];
            #pragma unroll
            for (int ni = 0; ni < 4; ++ni) {
                int row = wn * 64 + ni * 16 + lrow;
                ldmx4(bfr[ni], bbase + sw128((uint32_t)(row * 128 + ch16 * 16)));
            }
            #pragma unroll
            for (int mi = 0; mi < 2; ++mi)
                #pragma unroll
                for (int nj = 0; nj < 8; ++nj) {
                    const int ni = nj >> 1, sel = nj & 1;
                    mma16816(acc[mi][nj], afr[mi], bfr[ni][sel], bfr[ni][sel + 2]);
                }
        }
        __syncthreads();
    }

    // --- epilogue: fragment -> global, + bias ---
    const int r4 = lane >> 2;
    const int c2 = (lane & 3) * 2;
    #pragma unroll
    for (int mi = 0; mi < 2; ++mi) {
        const int gm0 = m0 + wm * 32 + mi * 16 + r4;
        const int gm1 = gm0 + 8;
        #pragma unroll
        for (int nj = 0; nj < 8; ++nj) {
            const int gn = n0 + wn * 64 + nj * 8 + c2;
            float b0 = 0.f, b1 = 0.f;
            if (gn < N)     b0 = bias[gn];
            if (gn + 1 < N) b1 = bias[gn + 1];
            if (gm0 < M) {
                float* row = C + (size_t)gm0 * ldc;
                if (gn < N)     row[gn]     = acc[mi][nj][0] + b0;
                if (gn + 1 < N) row[gn + 1] = acc[mi][nj][1] + b1;
            }
            if (gm1 < M) {
                float* row = C + (size_t)gm1 * ldc;
                if (gn < N)     row[gn]     = acc[mi][nj][2] + b0;
                if (gn + 1 < N) row[gn + 1] = acc[mi][nj][3] + b1;
            }
        }
    }
}

// ---------------------------------------------------------------------------
// Persistent recurrence (unchanged from passing round)
// ---------------------------------------------------------------------------
__device__ __forceinline__ float sigmoidf_(float x) { return 1.0f / (1.0f + __expf(-x)); }

__device__ __forceinline__ void grid_barrier()
{
    __syncthreads();
    if (threadIdx.x == 0) {
        __threadfence();
        unsigned gen = g_bar_gen;
        if (atomicAdd(&g_bar_count, 1u) == RNN_CTAS - 1) {
            atomicExch(&g_bar_count, 0u);
            __threadfence();
            g_bar_gen = gen + 1;
        } else {
            while (g_bar_gen == gen) { __nanosleep(64); }
        }
        __threadfence();
    }
    __syncthreads();
}

__device__ __forceinline__ void fma16(float4& a, const float4 w,
                                      const float4& x0, const float4& x1,
                                      const float4& x2, const float4& x3)
{
    a.x = fmaf(x0.x, w.x, a.x); a.y = fmaf(x0.y, w.x, a.y); a.z = fmaf(x0.z, w.x, a.z); a.w = fmaf(x0.w, w.x, a.w);
    a.x = fmaf(x1.x, w.y, a.x); a.y = fmaf(x1.y, w.y, a.y); a.z = fmaf(x1.z, w.y, a.z); a.w = fmaf(x1.w, w.y, a.w);
    a.x = fmaf(x2.x, w.z, a.x); a.y = fmaf(x2.y, w.z, a.y); a.z = fmaf(x2.z, w.z, a.z); a.w = fmaf(x2.w, w.z, a.w);
    a.x = fmaf(x3.x, w.w, a.x); a.y = fmaf(x3.y, w.w, a.y); a.z = fmaf(x3.z, w.w, a.z); a.w = fmaf(x3.w, w.w, a.w);
}

__global__ void __launch_bounds__(256, 1)
rnn_persistent(const float* __restrict__ Whh0, const float* __restrict__ bhh0,
               const float* __restrict__ Wih1, const float* __restrict__ bih1,
               const float* __restrict__ Whh1, const float* __restrict__ bhh1,
               const float* __restrict__ G0,   float* __restrict__ H1)
{
    __shared__ float red[24 * 256];

    const int tid = threadIdx.x;
    const int bq  = tid & 7;
    const int jl  = (tid >> 3) & 7;
    const int ks  = tid >> 6;
    const int j   = blockIdx.x * 8 + jl;
    const int b0  = bq << 2;
    const int kb  = ks << 8;

    const float4* w0r  = (const float4*)(Whh0 + (size_t)j * HH + kb);
    const float4* w0z  = (const float4*)(Whh0 + (size_t)(HH + j) * HH + kb);
    const float4* w0n  = (const float4*)(Whh0 + (size_t)(2 * HH + j) * HH + kb);
    const float4* w1ir = (const float4*)(Wih1 + (size_t)j * HH + kb);
    const float4* w1iz = (const float4*)(Wih1 + (size_t)(HH + j) * HH + kb);
    const float4* w1in = (const float4*)(Wih1 + (size_t)(2 * HH + j) * HH + kb);
    const float4* w1hr = (const float4*)(Whh1 + (size_t)j * HH + kb);
    const float4* w1hz = (const float4*)(Whh1 + (size_t)(HH + j) * HH + kb);
    const float4* w1hn = (const float4*)(Whh1 + (size_t)(2 * HH + j) * HH + kb);

    for (int t = 0; t < TT; ++t) {
        const int cur = t & 1, nxt = cur ^ 1;
        const float* h0c = g_h0T[cur];
        float*       h0n = g_h0T[nxt];
        const float* h1c = g_h1T[cur];
        float*       h1n = g_h1T[nxt];

        {
            float4 ar = {0,0,0,0}, az = {0,0,0,0}, an = {0,0,0,0};
            const float4* xp = (const float4*)(h0c + kb * BB) + bq;
            #pragma unroll 4
            for (int kk = 0; kk < 64; ++kk) {
                float4 wr = w0r[kk], wz = w0z[kk], wn = w0n[kk];
                float4 x0 = xp[(kk * 4 + 0) * 8];
                float4 x1 = xp[(kk * 4 + 1) * 8];
                float4 x2 = xp[(kk * 4 + 2) * 8];
                float4 x3 = xp[(kk * 4 + 3) * 8];
                fma16(ar, wr, x0, x1, x2, x3);
                fma16(az, wz, x0, x1, x2, x3);
                fma16(an, wn, x0, x1, x2, x3);
            }
            float vals[12] = {ar.x, ar.y, ar.z, ar.w,
                              az.x, az.y, az.z, az.w,
                              an.x, an.y, an.z, an.w};
            #pragma unroll
            for (int c = 0; c < 12; ++c) red[c * 256 + tid] = vals[c];
            __syncthreads();

            if (tid < 64) {
                float s[12];
                #pragma unroll
                for (int c = 0; c < 12; ++c)
                    s[c] = red[c * 256 + tid]       + red[c * 256 + tid + 64]
                         + red[c * 256 + tid + 128] + red[c * 256 + tid + 192];
                const float bhr = bhh0[j], bhz = bhh0[HH + j], bhn = bhh0[2 * HH + j];
                float hold[4];
                *(float4*)hold = *(const float4*)(h0c + j * BB + b0);
                float hnew[4];
                #pragma unroll
                for (int i = 0; i < 4; ++i) {
                    const int b = b0 + i;
                    const float* gi = G0 + ((size_t)b * TT + t) * GG;
                    float r = sigmoidf_(gi[j]          + s[i]     + bhr);
                    float z = sigmoidf_(gi[HH + j]     + s[4 + i] + bhz);
                    float n = tanhf    (gi[2 * HH + j] + r * (s[8 + i] + bhn));
                    hnew[i] = n + z * (hold[i] - n);
                }
                *(float4*)(h0n + j * BB + b0) = *(float4*)hnew;
            }
        }
        grid_barrier();

        {
            float4 air = {0,0,0,0}, aiz = {0,0,0,0}, ain = {0,0,0,0};
            float4 ahr = {0,0,0,0}, ahz = {0,0,0,0}, ahn = {0,0,0,0};
            const float4* xp = (const float4*)(h0n + kb * BB) + bq;
            const float4* hp = (const float4*)(h1c + kb * BB) + bq;
            #pragma unroll 2
            for (int kk = 0; kk < 64; ++kk) {
                float4 wir = w1ir[kk], wiz = w1iz[kk], win = w1in[kk];
                float4 whr = w1hr[kk], whz = w1hz[kk], whn = w1hn[kk];
                float4 x0 = xp[(kk * 4 + 0) * 8];
                float4 x1 = xp[(kk * 4 + 1) * 8];
                float4 x2 = xp[(kk * 4 + 2) * 8];
                float4 x3 = xp[(kk * 4 + 3) * 8];
                fma16(air, wir, x0, x1, x2, x3);
                fma16(aiz, wiz, x0, x1, x2, x3);
                fma16(ain, win, x0, x1, x2, x3);
                float4 h0_ = hp[(kk * 4 + 0) * 8];
                float4 h1_ = hp[(kk * 4 + 1) * 8];
                float4 h2_ = hp[(kk * 4 + 2) * 8];
                float4 h3_ = hp[(kk * 4 + 3) * 8];
                fma16(ahr, whr, h0_, h1_, h2_, h3_);
                fma16(ahz, whz, h0_, h1_, h2_, h3_);
                fma16(ahn, whn, h0_, h1_, h2_, h3_);
            }
            float vals[24] = {air.x, air.y, air.z, air.w,  aiz.x, aiz.y, aiz.z, aiz.w,
                              ain.x, ain.y, ain.z, ain.w,  ahr.x, ahr.y, ahr.z, ahr.w,
                              ahz.x, ahz.y, ahz.z, ahz.w,  ahn.x, ahn.y, ahn.z, ahn.w};
            #pragma unroll
            for (int c = 0; c < 24; ++c) red[c * 256 + tid] = vals[c];
            __syncthreads();

            if (tid < 64) {
                float s[24];
                #pragma unroll
                for (int c = 0; c < 24; ++c)
                    s[c] = red[c * 256 + tid]       + red[c * 256 + tid + 64]
                         + red[c * 256 + tid + 128] + red[c * 256 + tid + 192];
                const float bir = bih1[j], biz = bih1[HH + j], bin_ = bih1[2 * HH + j];
                const float bhr = bhh1[j], bhz = bhh1[HH + j], bhn  = bhh1[2 * HH + j];
                float hold[4];
                *(float4*)hold = *(const float4*)(h1c + j * BB + b0);
                float hnew[4];
                #pragma unroll
                for (int i = 0; i < 4; ++i) {
                    const int b = b0 + i;
                    float r = sigmoidf_((s[i]      + bir) + (s[12 + i] + bhr));
                    float z = sigmoidf_((s[4 + i]  + biz) + (s[16 + i] + bhz));
                    float n = tanhf    ((s[8 + i]  + bin_) + r * (s[20 + i] + bhn));
                    hnew[i] = n + z * (hold[i] - n);
                    H1[((size_t)b * TT + t) * HH + j] = hnew[i];
                }
                *(float4*)(h1n + j * BB + b0) = *(float4*)hnew;
            }
        }
        grid_barrier();
    }
}

// ---------------------------------------------------------------------------
// Launch
// ---------------------------------------------------------------------------
extern "C" void kernel_launch(void* const* d_in, const int* in_sizes, int n_in,
                              void* d_out, int out_size)
{
    const int*   y     = nullptr;
    const float* embed = nullptr;
    const float* initS = nullptr;
    const float* Wih   = nullptr;
    const float* Whh   = nullptr;
    const float* bih   = nullptr;
    const float* bhh   = nullptr;
    const float* Wout  = nullptr;
    const float* bout  = nullptr;

    for (int i = 0; i < n_in; ++i) {
        long long s = in_sizes[i];
        if (s == (long long)BB * UU && !y)               y     = (const int*)d_in[i];
        else if (s == (long long)VV * HH) {
            if (!embed)                                  embed = (const float*)d_in[i];
            else if (!Wout)                              Wout  = (const float*)d_in[i];
        }
        else if (s == 2LL * HH && !initS)                initS = (const float*)d_in[i];
        else if (s == 2LL * GG * HH) {
            if (!Wih)                                    Wih   = (const float*)d_in[i];
            else if (!Whh)                               Whh   = (const float*)d_in[i];
        }
        else if (s == 2LL * GG) {
            if (!bih)                                    bih   = (const float*)d_in[i];
            else if (!bhh)                               bhh   = (const float*)d_in[i];
        }
        else if (s == (long long)VV && !bout)            bout  = (const float*)d_in[i];
    }

    __nv_bfloat16 *pA = nullptr, *pB = nullptr;
    float *pG0 = nullptr, *pH1 = nullptr;
    cudaGetSymbolAddress((void**)&pA,  g_Asplit);
    cudaGetSymbolAddress((void**)&pB,  g_Bsplit);
    cudaGetSymbolAddress((void**)&pG0, g_G0);
    cudaGetSymbolAddress((void**)&pH1, g_H1);

    cudaFuncSetAttribute(mma_gemm_bf16,
                         cudaFuncAttributeMaxDynamicSharedMemorySize, GEMM_DYN_SMEM);

    const int MT = (MM + 127) / 128;          // 65

    // 1) embeddings -> A' (hi|lo|hi)
    gather_split<<<MM, 256>>>(y, embed, pA);

    // 2) Wih0 -> B' (hi|hi|lo)
    split_mat<<<(GG * HH + 255) / 256, 256>>>(Wih, pB, GG, 2);

    // 3) init recurrent state
    init_states<<<128, 256>>>(initS);

    // 4) gi0 = X @ Wih0^T + bih0  (HMMA tensor cores, hi/lo split-K)
    mma_gemm_bf16<<<dim3(GG / 128, MT), 256, GEMM_DYN_SMEM>>>(
        pA, pB, bih, pG0, MM, GG, GG);

    // 5) 257-step recurrence -> H1 (fp32)
    rnn_persistent<<<RNN_CTAS, 256>>>(
        Whh, bhh,
        Wih + (size_t)GG * HH, bih + GG,
        Whh + (size_t)GG * HH, bhh + GG,
        pG0, pH1);

    // 6) H1 -> A' (hi|lo|hi),  Wout -> B' (hi|hi|lo)
    split_mat<<<(MM * HH + 255) / 256, 256>>>(pH1, pA, MM, 1);
    split_mat<<<(VV * HH + 255) / 256, 256>>>(Wout, pB, VV, 2);

    // 7) OUT = H1 @ Wout^T + bout -> d_out (B, U+1, V)
    mma_gemm_bf16<<<dim3((VV + 127) / 128, MT), 256, GEMM_DYN_SMEM>>>(
        pA, pB, bout, (float*)d_out, MM, VV, VV);

    (void)n_in; (void)out_size;
}

// round 17
// speedup vs baseline: 2.2879x; 1.8756x over previous
#include <cuda_runtime.h>
#include <cuda_bf16.h>
#include <cstdint>
#include <cstddef>

// ---------------------------------------------------------------------------
// Problem constants
// ---------------------------------------------------------------------------
#define BB    32
#define UU    256
#define TT    257
#define HH    1024
#define GG    3072
#define VV    10001
#define MM    (BB * TT)       // 8224
#define KSPL  3072            // split K for big GEMMs (3 x 1024)

#define KSP   3072            // split K for recurrence
#define KC    256             // K chunk (bf16 elems) streamed per stage
#define NCH   12              // KSP / KC
#define ROWB  512             // bytes per smem row (KC * 2)

#define RNN_CTAS 128

// ---------------------------------------------------------------------------
// Scratch (device globals -- no runtime allocation allowed)
// ---------------------------------------------------------------------------
__device__ __align__(16) __nv_bfloat16 g_Asplit[(size_t)MM * KSPL];   // 50.5 MB
__device__ __align__(16) __nv_bfloat16 g_Bsplit[(size_t)VV * KSPL];   // 61.4 MB
__device__ __align__(16) float g_G0[(size_t)MM * GG];                 // gi0
__device__ __align__(16) float g_H1[(size_t)MM * HH];                 // layer-1 states
__device__ __align__(16) __nv_bfloat16 g_W0s [(size_t)GG * KSP];      // Whh0 split
__device__ __align__(16) __nv_bfloat16 g_W1is[(size_t)GG * KSP];      // Wih1 split
__device__ __align__(16) __nv_bfloat16 g_W1hs[(size_t)GG * KSP];      // Whh1 split
__device__ __align__(16) __nv_bfloat16 g_h0s[2][BB * KSP];            // split h0 state
__device__ __align__(16) __nv_bfloat16 g_h1s[2][BB * KSP];            // split h1 state
__device__ unsigned          g_bar_count;
__device__ volatile unsigned g_bar_gen;

// ---------------------------------------------------------------------------
// Base-ISA helpers (mma.sync / ldmatrix / cp.async only -- plain sm_103 ok)
// ---------------------------------------------------------------------------
__device__ __forceinline__ uint32_t smem_u32(const void* p) {
    uint32_t a;
    asm("{ .reg .u64 t; cvta.to.shared.u64 t, %1; cvt.u32.u64 %0, t; }" : "=r"(a) : "l"(p));
    return a;
}
__device__ __forceinline__ uint32_t sw128(uint32_t x) { return x ^ ((x >> 3) & 0x70); }

__device__ __forceinline__ void cp_async16(uint32_t saddr, const void* gaddr, uint32_t src_bytes) {
    asm volatile("cp.async.cg.shared.global [%0], [%1], 16, %2;"
                 :: "r"(saddr), "l"(gaddr), "r"(src_bytes) : "memory");
}
#define CP_COMMIT()   asm volatile("cp.async.commit_group;" ::: "memory")
#define CP_WAIT(n)    asm volatile("cp.async.wait_group %0;" :: "n"(n) : "memory")

__device__ __forceinline__ void ldmx4(uint32_t* r, uint32_t addr) {
    asm volatile("ldmatrix.sync.aligned.m8n8.x4.shared.b16 {%0,%1,%2,%3}, [%4];"
                 : "=r"(r[0]), "=r"(r[1]), "=r"(r[2]), "=r"(r[3]) : "r"(addr));
}
__device__ __forceinline__ void ldmx2(uint32_t* r, uint32_t addr) {
    asm volatile("ldmatrix.sync.aligned.m8n8.x2.shared.b16 {%0,%1}, [%2];"
                 : "=r"(r[0]), "=r"(r[1]) : "r"(addr));
}
__device__ __forceinline__ void mma16816(float* c, const uint32_t* a,
                                         uint32_t b0, uint32_t b1) {
    asm volatile("mma.sync.aligned.m16n8k16.row.col.f32.bf16.bf16.f32 "
                 "{%0,%1,%2,%3}, {%4,%5,%6,%7}, {%8,%9}, {%0,%1,%2,%3};"
                 : "+f"(c[0]), "+f"(c[1]), "+f"(c[2]), "+f"(c[3])
                 : "r"(a[0]), "r"(a[1]), "r"(a[2]), "r"(a[3]), "r"(b0), "r"(b1));
}

// swizzled smem address: row*ROWB, 16B unit index XORed with (row & 7)
__device__ __forceinline__ uint32_t swa(uint32_t base, int row, int u) {
    return base + row * ROWB + (((u ^ (row & 7)) & 31) << 4);
}

__device__ __forceinline__ float sigmoidf_(float x) { return 1.0f / (1.0f + __expf(-x)); }

__device__ __forceinline__ void grid_barrier()
{
    __syncthreads();
    if (threadIdx.x == 0) {
        __threadfence();
        unsigned gen = g_bar_gen;
        if (atomicAdd(&g_bar_count, 1u) == RNN_CTAS - 1) {
            atomicExch(&g_bar_count, 0u);
            __threadfence();
            g_bar_gen = gen + 1;
        } else {
            while (g_bar_gen == gen) { __nanosleep(64); }
        }
        __threadfence();
    }
    __syncthreads();
}

// ---------------------------------------------------------------------------
// Split helpers: x -> (hi, lo) bf16, K-concatenated layout
// A-style row: [hi | lo | hi]   (lo_slot = 1)
// B-style row: [hi | hi | lo]   (lo_slot = 2)
// ---------------------------------------------------------------------------
__global__ void split_mat(const float* __restrict__ src, __nv_bfloat16* __restrict__ dst,
                          int R, int lo_slot)
{
    int idx = blockIdx.x * 256 + threadIdx.x;
    if (idx >= R * HH) return;
    int r = idx >> 10, k = idx & 1023;
    float x = src[idx];
    __nv_bfloat16 hi = __float2bfloat16(x);
    __nv_bfloat16 lo = __float2bfloat16(x - __bfloat162float(hi));
    __nv_bfloat16* row = dst + (size_t)r * KSPL;
    row[k]          = (lo_slot == 0) ? lo : hi;
    row[HH + k]     = (lo_slot == 1) ? lo : hi;
    row[2 * HH + k] = (lo_slot == 2) ? lo : hi;
}

__global__ void gather_split(const int* __restrict__ y,
                             const float* __restrict__ embed,
                             __nv_bfloat16* __restrict__ dst)
{
    int m = blockIdx.x;                       // m = b*257 + t
    int b = m / TT, t = m % TT;
    int tok = (t == 0) ? (VV - 1) : y[b * UU + (t - 1)];
    const float* src = embed + (size_t)tok * HH;
    __nv_bfloat16* row = dst + (size_t)m * KSPL;
    for (int k = threadIdx.x; k < HH; k += 256) {
        float x = src[k];
        __nv_bfloat16 hi = __float2bfloat16(x);
        __nv_bfloat16 lo = __float2bfloat16(x - __bfloat162float(hi));
        row[k] = hi; row[HH + k] = lo; row[2 * HH + k] = hi;
    }
}

// initial split states from init_state (broadcast over batch)
__global__ void init_split(const float* __restrict__ initS)
{
    int idx = blockIdx.x * 256 + threadIdx.x;   // 0 .. 32*1024-1
    int b = idx >> 10, k = idx & 1023;
    float x0 = initS[k];
    float x1 = initS[HH + k];
    __nv_bfloat16 h0hi = __float2bfloat16(x0);
    __nv_bfloat16 h0lo = __float2bfloat16(x0 - __bfloat162float(h0hi));
    __nv_bfloat16 h1hi = __float2bfloat16(x1);
    __nv_bfloat16 h1lo = __float2bfloat16(x1 - __bfloat162float(h1hi));
    __nv_bfloat16* d0 = g_h0s[0] + (size_t)b * KSP;
    __nv_bfloat16* d1 = g_h1s[0] + (size_t)b * KSP;
    d0[k] = h0hi; d0[HH + k] = h0lo; d0[2 * HH + k] = h0hi;
    d1[k] = h1hi; d1[HH + k] = h1lo; d1[2 * HH + k] = h1hi;
}

// ---------------------------------------------------------------------------
// bf16 HMMA GEMM:  C[M][N] = A'[M][3072] * B'[N][3072]^T + bias[N] (fp32 acc)
// (unchanged from passing round)
// ---------------------------------------------------------------------------
#define GEMM_DYN_SMEM 65536

__global__ void __launch_bounds__(256, 1)
mma_gemm_bf16(const __nv_bfloat16* __restrict__ A,
              const __nv_bfloat16* __restrict__ Bm,
              const float* __restrict__ bias,
              float* __restrict__ C,
              int M, int N, int ldc)
{
    constexpr int KCH = KSPL / 64;
    extern __shared__ __align__(16) char dyn[];

    const int tid  = threadIdx.x;
    const int wid  = tid >> 5;
    const int lane = tid & 31;
    const int wm   = wid & 3;
    const int wn   = wid >> 2;
    const int m0 = blockIdx.y * 128;
    const int n0 = blockIdx.x * 128;

    const uint32_t sbase = smem_u32(dyn);
    const uint32_t offA[2] = { 0u, 16384u };
    const uint32_t offB[2] = { 32768u, 49152u };

    float acc[2][8][4];
    #pragma unroll
    for (int mi = 0; mi < 2; ++mi)
        #pragma unroll
        for (int nj = 0; nj < 8; ++nj)
            #pragma unroll
            for (int q = 0; q < 4; ++q) acc[mi][nj][q] = 0.0f;

    auto issue_stage = [&](int ch) {
        const int buf = ch & 1;
        #pragma unroll
        for (int i = 0; i < 4; ++i) {
            int idx = tid + i * 256;
            int r = idx >> 3, u = idx & 7;
            uint32_t so = sw128((uint32_t)(r * 128 + u * 16));
            int ra = (m0 + r < M) ? (m0 + r) : 0;
            uint32_t sza = (m0 + r < M) ? 16u : 0u;
            cp_async16(sbase + offA[buf] + so,
                       A + (size_t)ra * KSPL + ch * 64 + u * 8, sza);
            int rb = (n0 + r < N) ? (n0 + r) : 0;
            uint32_t szb = (n0 + r < N) ? 16u : 0u;
            cp_async16(sbase + offB[buf] + so,
                       Bm + (size_t)rb * KSPL + ch * 64 + u * 8, szb);
        }
        CP_COMMIT();
    };

    issue_stage(0);

    for (int ch = 0; ch < KCH; ++ch) {
        const int buf = ch & 1;
        if (ch + 1 < KCH) { issue_stage(ch + 1); CP_WAIT(1); }
        else              { CP_WAIT(0); }
        __syncthreads();

        const uint32_t abase = sbase + offA[buf];
        const uint32_t bbase = sbase + offB[buf];
        const int lrow = lane & 15;
        const int lch  = lane >> 4;

        #pragma unroll
        for (int kk = 0; kk < 4; ++kk) {
            const int ch16 = kk * 2 + lch;
            uint32_t afr[2][4];
            #pragma unroll
            for (int mi = 0; mi < 2; ++mi) {
                int row = wm * 32 + mi * 16 + lrow;
                ldmx4(afr[mi], abase + sw128((uint32_t)(row * 128 + ch16 * 16)));
            }
            uint32_t bfr[4][4];
            #pragma unroll
            for (int ni = 0; ni < 4; ++ni) {
                int row = wn * 64 + ni * 16 + lrow;
                ldmx4(bfr[ni], bbase + sw128((uint32_t)(row * 128 + ch16 * 16)));
            }
            #pragma unroll
            for (int mi = 0; mi < 2; ++mi)
                #pragma unroll
                for (int nj = 0; nj < 8; ++nj) {
                    const int ni = nj >> 1, sel = nj & 1;
                    mma16816(acc[mi][nj], afr[mi], bfr[ni][sel], bfr[ni][sel + 2]);
                }
        }
        __syncthreads();
    }

    const int r4 = lane >> 2;
    const int c2 = (lane & 3) * 2;
    #pragma unroll
    for (int mi = 0; mi < 2; ++mi) {
        const int gm0 = m0 + wm * 32 + mi * 16 + r4;
        const int gm1 = gm0 + 8;
        #pragma unroll
        for (int nj = 0; nj < 8; ++nj) {
            const int gn = n0 + wn * 64 + nj * 8 + c2;
            float b0 = 0.f, b1 = 0.f;
            if (gn < N)     b0 = bias[gn];
            if (gn + 1 < N) b1 = bias[gn + 1];
            if (gm0 < M) {
                float* row = C + (size_t)gm0 * ldc;
                if (gn < N)     row[gn]     = acc[mi][nj][0] + b0;
                if (gn + 1 < N) row[gn + 1] = acc[mi][nj][1] + b1;
            }
            if (gm1 < M) {
                float* row = C + (size_t)gm1 * ldc;
                if (gn < N)     row[gn]     = acc[mi][nj][2] + b0;
                if (gn + 1 < N) row[gn + 1] = acc[mi][nj][3] + b1;
            }
        }
    }
}

// ---------------------------------------------------------------------------
// Tensor-core persistent recurrence.
// 128 CTAs x 256 threads. CTA owns 8 hidden units j (gate rows j,1024+j,2048+j).
// Per step:
//   phase A: gh0[32,24] = h0'[32,3072] @ Whh0'[24,3072]^T  (HMMA, 8-way warp
//            K-split, cp.async double-buffered K chunks) -> reduce -> gates ->
//            h0 (fp32 regs) -> publish split h0' global
//   phase B: gi1 (from h0') and gh1 (from h1') likewise -> gates -> h1,
//            write H1 fp32 for the OUT GEMM, publish split h1'.
// ---------------------------------------------------------------------------
#define RNN_DYN_SMEM 114688   // phase B: 2 x (48+64 rows x 512B)

__global__ void __launch_bounds__(256, 1)
rnn_tc(const float* __restrict__ G0, float* __restrict__ H1,
       const float* __restrict__ initS,
       const float* __restrict__ bhh0,
       const float* __restrict__ bih1, const float* __restrict__ bhh1)
{
    extern __shared__ __align__(16) char dyn[];
    const uint32_t sb = smem_u32(dyn);

    const int tid  = threadIdx.x;
    const int w    = tid >> 5;
    const int lane = tid & 31;
    const int j0   = blockIdx.x * 8;

    // gate-math ownership: thread -> (batch gb, hidden j0+gj)
    const int gb = tid >> 3;
    const int gj = tid & 7;
    const int j  = j0 + gj;

    float h0 = initS[j];
    float h1 = initS[HH + j];
    const float bh0r = bhh0[j], bh0z = bhh0[HH + j], bh0n = bhh0[2 * HH + j];
    const float bi1r = bih1[j], bi1z = bih1[HH + j], bi1n = bih1[2 * HH + j];
    const float bh1r = bhh1[j], bh1z = bhh1[HH + j], bh1n = bhh1[2 * HH + j];

    const int lr16 = lane & 15, lc2 = lane >> 4;        // ldmx4 lane mapping
    const int lr8  = lane & 7,  lc1 = (lane >> 3) & 1;  // ldmx2 lane mapping

    for (int t = 0; t < TT; ++t) {
        const int cur = t & 1, nxt = cur ^ 1;
        const __nv_bfloat16* h0c = g_h0s[cur];
        const __nv_bfloat16* h1c = g_h1s[cur];

        // ============================ phase A ============================
        {
            auto stage = [&](int ch) {
                const uint32_t base = sb + (uint32_t)(ch & 1) * 28672u;
                #pragma unroll
                for (int i = 0; i < 7; ++i) {
                    int idx = tid + i * 256;
                    if (idx < 768) {                       // W tile: 24 rows
                        int row = idx >> 5, u = idx & 31;
                        int absr = (row >> 3) * HH + j0 + (row & 7);
                        cp_async16(swa(base, row, u),
                                   g_W0s + (size_t)absr * KSP + ch * KC + u * 8, 16);
                    } else {                               // A tile: 32 rows
                        int i2 = idx - 768;
                        int b = i2 >> 5, u = i2 & 31;
                        cp_async16(swa(base + 24 * ROWB, b, u),
                                   h0c + (size_t)b * KSP + ch * KC + u * 8, 16);
                    }
                }
                CP_COMMIT();
            };

            float acc[2][3][4] = {};
            stage(0);
            for (int ch = 0; ch < NCH; ++ch) {
                if (ch + 1 < NCH) { stage(ch + 1); CP_WAIT(1); }
                else              { CP_WAIT(0); }
                __syncthreads();
                const uint32_t Wb = sb + (uint32_t)(ch & 1) * 28672u;
                const uint32_t Ab = Wb + 24 * ROWB;
                #pragma unroll
                for (int kk = 0; kk < 2; ++kk) {
                    const int k16 = w * 2 + kk;            // warp K-split
                    uint32_t afr[2][4], brz[4], bn[2];
                    #pragma unroll
                    for (int mi = 0; mi < 2; ++mi)
                        ldmx4(afr[mi], swa(Ab, mi * 16 + lr16, k16 * 2 + lc2));
                    ldmx4(brz, swa(Wb, lr16, k16 * 2 + lc2));
                    ldmx2(bn,  swa(Wb, 16 + lr8, k16 * 2 + lc1));
                    #pragma unroll
                    for (int mi = 0; mi < 2; ++mi) {
                        mma16816(acc[mi][0], afr[mi], brz[0], brz[2]);
                        mma16816(acc[mi][1], afr[mi], brz[1], brz[3]);
                        mma16816(acc[mi][2], afr[mi], bn[0],  bn[1]);
                    }
                }
                __syncthreads();
            }

            // cross-warp reduction through SMEM (reuses pipeline area)
            float* red = (float*)dyn;
            #pragma unroll
            for (int mi = 0; mi < 2; ++mi)
                #pragma unroll
                for (int g = 0; g < 3; ++g)
                    #pragma unroll
                    for (int q = 0; q < 4; ++q) {
                        int b  = mi * 16 + ((q >> 1) << 3) + (lane >> 2);
                        int jl = ((lane & 3) << 1) + (q & 1);
                        red[((w * 3 + g) * 32 + b) * 8 + jl] = acc[mi][g][q];
                    }
            __syncthreads();

            float s0 = 0.f, s1 = 0.f, s2 = 0.f;
            #pragma unroll
            for (int ww = 0; ww < 8; ++ww) {
                s0 += red[((ww * 3 + 0) * 32 + gb) * 8 + gj];
                s1 += red[((ww * 3 + 1) * 32 + gb) * 8 + gj];
                s2 += red[((ww * 3 + 2) * 32 + gb) * 8 + gj];
            }
            const float* gi = G0 + ((size_t)gb * TT + t) * GG;
            float r = sigmoidf_(gi[j]          + s0 + bh0r);
            float z = sigmoidf_(gi[HH + j]     + s1 + bh0z);
            float n = tanhf    (gi[2 * HH + j] + r * (s2 + bh0n));
            h0 = n + z * (h0 - n);
            __nv_bfloat16 hi = __float2bfloat16(h0);
            __nv_bfloat16 lo = __float2bfloat16(h0 - __bfloat162float(hi));
            __nv_bfloat16* d = g_h0s[nxt] + (size_t)gb * KSP;
            d[j] = hi; d[HH + j] = lo; d[2 * HH + j] = hi;
        }
        grid_barrier();

        // ============================ phase B ============================
        {
            const __nv_bfloat16* h0n_ = g_h0s[nxt];
            auto stage = [&](int ch) {
                const uint32_t base = sb + (uint32_t)(ch & 1) * 57344u;
                #pragma unroll
                for (int i = 0; i < 14; ++i) {
                    int idx = tid + i * 256;
                    if (idx < 1536) {                      // W: Wih1 rows 0-23, Whh1 rows 24-47
                        int row = idx >> 5, u = idx & 31;
                        const __nv_bfloat16* W = (row < 24) ? g_W1is : g_W1hs;
                        int lr = (row < 24) ? row : row - 24;
                        int absr = (lr >> 3) * HH + j0 + (lr & 7);
                        cp_async16(swa(base, row, u),
                                   W + (size_t)absr * KSP + ch * KC + u * 8, 16);
                    } else if (idx < 2560) {               // A0: h0new split
                        int i2 = idx - 1536;
                        int b = i2 >> 5, u = i2 & 31;
                        cp_async16(swa(base + 48 * ROWB, b, u),
                                   h0n_ + (size_t)b * KSP + ch * KC + u * 8, 16);
                    } else {                               // A1: h1 split
                        int i2 = idx - 2560;
                        int b = i2 >> 5, u = i2 & 31;
                        cp_async16(swa(base + 80 * ROWB, b, u),
                                   h1c + (size_t)b * KSP + ch * KC + u * 8, 16);
                    }
                }
                CP_COMMIT();
            };

            float aI[2][3][4] = {}, aH[2][3][4] = {};
            stage(0);
            for (int ch = 0; ch < NCH; ++ch) {
                if (ch + 1 < NCH) { stage(ch + 1); CP_WAIT(1); }
                else              { CP_WAIT(0); }
                __syncthreads();
                const uint32_t Wb  = sb + (uint32_t)(ch & 1) * 57344u;
                const uint32_t A0b = Wb + 48 * ROWB;
                const uint32_t A1b = Wb + 80 * ROWB;
                #pragma unroll
                for (int kk = 0; kk < 2; ++kk) {
                    const int k16 = w * 2 + kk;
                    uint32_t a0[2][4], a1[2][4], bi4[4], bin2[2], bh4[4], bhn2[2];
                    #pragma unroll
                    for (int mi = 0; mi < 2; ++mi) {
                        ldmx4(a0[mi], swa(A0b, mi * 16 + lr16, k16 * 2 + lc2));
                        ldmx4(a1[mi], swa(A1b, mi * 16 + lr16, k16 * 2 + lc2));
                    }
                    ldmx4(bi4,  swa(Wb, lr16,      k16 * 2 + lc2));
                    ldmx2(bin2, swa(Wb, 16 + lr8,  k16 * 2 + lc1));
                    ldmx4(bh4,  swa(Wb, 24 + lr16, k16 * 2 + lc2));
                    ldmx2(bhn2, swa(Wb, 40 + lr8,  k16 * 2 + lc1));
                    #pragma unroll
                    for (int mi = 0; mi < 2; ++mi) {
                        mma16816(aI[mi][0], a0[mi], bi4[0],  bi4[2]);
                        mma16816(aI[mi][1], a0[mi], bi4[1],  bi4[3]);
                        mma16816(aI[mi][2], a0[mi], bin2[0], bin2[1]);
                        mma16816(aH[mi][0], a1[mi], bh4[0],  bh4[2]);
                        mma16816(aH[mi][1], a1[mi], bh4[1],  bh4[3]);
                        mma16816(aH[mi][2], a1[mi], bhn2[0], bhn2[1]);
                    }
                }
                __syncthreads();
            }

            float* red = (float*)dyn;
            #pragma unroll
            for (int mi = 0; mi < 2; ++mi)
                #pragma unroll
                for (int g = 0; g < 3; ++g)
                    #pragma unroll
                    for (int q = 0; q < 4; ++q) {
                        int b  = mi * 16 + ((q >> 1) << 3) + (lane >> 2);
                        int jl = ((lane & 3) << 1) + (q & 1);
                        red[((w * 6 + g) * 32 + b) * 8 + jl]       = aI[mi][g][q];
                        red[((w * 6 + 3 + g) * 32 + b) * 8 + jl]   = aH[mi][g][q];
                    }
            __syncthreads();

            float sI0 = 0.f, sI1 = 0.f, sI2 = 0.f, sH0 = 0.f, sH1 = 0.f, sH2 = 0.f;
            #pragma unroll
            for (int ww = 0; ww < 8; ++ww) {
                sI0 += red[((ww * 6 + 0) * 32 + gb) * 8 + gj];
                sI1 += red[((ww * 6 + 1) * 32 + gb) * 8 + gj];
                sI2 += red[((ww * 6 + 2) * 32 + gb) * 8 + gj];
                sH0 += red[((ww * 6 + 3) * 32 + gb) * 8 + gj];
                sH1 += red[((ww * 6 + 4) * 32 + gb) * 8 + gj];
                sH2 += red[((ww * 6 + 5) * 32 + gb) * 8 + gj];
            }
            float r = sigmoidf_((sI0 + bi1r) + (sH0 + bh1r));
            float z = sigmoidf_((sI1 + bi1z) + (sH1 + bh1z));
            float n = tanhf    ((sI2 + bi1n) + r * (sH2 + bh1n));
            h1 = n + z * (h1 - n);
            H1[((size_t)gb * TT + t) * HH + j] = h1;
            __nv_bfloat16 hi = __float2bfloat16(h1);
            __nv_bfloat16 lo = __float2bfloat16(h1 - __bfloat162float(hi));
            __nv_bfloat16* d = g_h1s[nxt] + (size_t)gb * KSP;
            d[j] = hi; d[HH + j] = lo; d[2 * HH + j] = hi;
        }
        grid_barrier();
    }
}

// ---------------------------------------------------------------------------
// Launch
// ---------------------------------------------------------------------------
extern "C" void kernel_launch(void* const* d_in, const int* in_sizes, int n_in,
                              void* d_out, int out_size)
{
    const int*   y     = nullptr;
    const float* embed = nullptr;
    const float* initS = nullptr;
    const float* Wih   = nullptr;
    const float* Whh   = nullptr;
    const float* bih   = nullptr;
    const float* bhh   = nullptr;
    const float* Wout  = nullptr;
    const float* bout  = nullptr;

    for (int i = 0; i < n_in; ++i) {
        long long s = in_sizes[i];
        if (s == (long long)BB * UU && !y)               y     = (const int*)d_in[i];
        else if (s == (long long)VV * HH) {
            if (!embed)                                  embed = (const float*)d_in[i];
            else if (!Wout)                              Wout  = (const float*)d_in[i];
        }
        else if (s == 2LL * HH && !initS)                initS = (const float*)d_in[i];
        else if (s == 2LL * GG * HH) {
            if (!Wih)                                    Wih   = (const float*)d_in[i];
            else if (!Whh)                               Whh   = (const float*)d_in[i];
        }
        else if (s == 2LL * GG) {
            if (!bih)                                    bih   = (const float*)d_in[i];
            else if (!bhh)                               bhh   = (const float*)d_in[i];
        }
        else if (s == (long long)VV && !bout)            bout  = (const float*)d_in[i];
    }

    __nv_bfloat16 *pA = nullptr, *pB = nullptr, *pW0 = nullptr, *pW1i = nullptr, *pW1h = nullptr;
    float *pG0 = nullptr, *pH1 = nullptr;
    cudaGetSymbolAddress((void**)&pA,   g_Asplit);
    cudaGetSymbolAddress((void**)&pB,   g_Bsplit);
    cudaGetSymbolAddress((void**)&pW0,  g_W0s);
    cudaGetSymbolAddress((void**)&pW1i, g_W1is);
    cudaGetSymbolAddress((void**)&pW1h, g_W1hs);
    cudaGetSymbolAddress((void**)&pG0,  g_G0);
    cudaGetSymbolAddress((void**)&pH1,  g_H1);

    cudaFuncSetAttribute(mma_gemm_bf16,
                         cudaFuncAttributeMaxDynamicSharedMemorySize, GEMM_DYN_SMEM);
    cudaFuncSetAttribute(rnn_tc,
                         cudaFuncAttributeMaxDynamicSharedMemorySize, RNN_DYN_SMEM);

    const int MT = (MM + 127) / 128;          // 65
    const int WB = (GG * HH + 255) / 256;     // weight-split grid

    // 1) embeddings -> A' (hi|lo|hi)
    gather_split<<<MM, 256>>>(y, embed, pA);

    // 2) split all weights used by tensor-core paths (B-style: hi|hi|lo)
    split_mat<<<WB, 256>>>(Wih, pB, GG, 2);                            // Wih0 for gi0
    split_mat<<<WB, 256>>>(Whh, pW0, GG, 2);                           // Whh0
    split_mat<<<WB, 256>>>(Wih + (size_t)GG * HH, pW1i, GG, 2);        // Wih1
    split_mat<<<WB, 256>>>(Whh + (size_t)GG * HH, pW1h, GG, 2);        // Whh1

    // 3) initial split states
    init_split<<<(BB * HH) / 256, 256>>>(initS);

    // 4) gi0 = X @ Wih0^T + bih0  (HMMA, hi/lo split-K)
    mma_gemm_bf16<<<dim3(GG / 128, MT), 256, GEMM_DYN_SMEM>>>(
        pA, pB, bih, pG0, MM, GG, GG);

    // 5) 257-step tensor-core recurrence -> H1 (fp32)
    rnn_tc<<<RNN_CTAS, 256, RNN_DYN_SMEM>>>(
        pG0, pH1, initS, bhh, bih + GG, bhh + GG);

    // 6) H1 -> A' (hi|lo|hi),  Wout -> B' (hi|hi|lo)
    split_mat<<<(MM * HH + 255) / 256, 256>>>(pH1, pA, MM, 1);
    split_mat<<<(VV * HH + 255) / 256, 256>>>(Wout, pB, VV, 2);

    // 7) OUT = H1 @ Wout^T + bout -> d_out (B, U+1, V)
    mma_gemm_bf16<<<dim3((VV + 127) / 128, MT), 256, GEMM_DYN_SMEM>>>(
        pA, pB, bout, (float*)d_out, MM, VV, VV);

    (void)n_in; (void)out_size;
}